// round 3
// baseline (speedup 1.0000x reference)
#include <cuda_runtime.h>

#define NB 256
#define NC 50000
#define ND 512
#define ND4 (ND / 4)          // 128 float4 per row
#define ALPHA_F 0.5f
#define ROWS_PB 8             // classes per block in k_centers

__device__ int g_labels[NB];
__device__ int g_counts[NC];

// ---------------------------------------------------------------- K0: zero counts (tiny)
__global__ void k_zero() {
    int i = blockIdx.x * blockDim.x + threadIdx.x;
    if (i < NC) g_counts[i] = 0;
}

// ---------------------------------------------------------------- K1: labels + counts
// onehot [NB, NC] f32 scanned as float4; 3.2M float4s; 4 per thread (MLP=4).
// grid = 3.2M / 1024 = 3125 blocks x 256 threads, exact.
__global__ __launch_bounds__(256) void k_find(const float4* __restrict__ oh) {
    int base = blockIdx.x * 1024 + threadIdx.x;
    float4 v[4];
    v[0] = __ldcs(oh + base);
    v[1] = __ldcs(oh + base + 256);
    v[2] = __ldcs(oh + base + 512);
    v[3] = __ldcs(oh + base + 768);
    #pragma unroll
    for (int k = 0; k < 4; k++) {
        float4 w = v[k];
        if (w.x != 0.0f || w.y != 0.0f || w.z != 0.0f || w.w != 0.0f) {
            int i = base + k * 256;
            int b = i / (NC / 4);
            int cb = (i - b * (NC / 4)) * 4;
            int off = (w.x != 0.0f) ? 0 : (w.y != 0.0f) ? 1 : (w.z != 0.0f) ? 2 : 3;
            int c = cb + off;
            g_labels[b] = c;                     // unique writer per sample row
            atomicAdd(&g_counts[c], 1);
        }
    }
}

// ---------------------------------------------------------------- K2: per-sample distance only
// One block (128 threads) per sample: result[b] = ||x[b] - centers[label[b]]||^2
__global__ void k_sample(const float* __restrict__ x,
                         const float* __restrict__ centers,
                         float* __restrict__ result) {
    __shared__ float s_warp[4];
    int b = blockIdx.x;
    int t = threadIdx.x;
    int lab = g_labels[b];

    float4 xv = ((const float4*)(x + (size_t)b * ND))[t];
    float4 cv = ((const float4*)(centers + (size_t)lab * ND))[t];

    float dx = xv.x - cv.x, dy = xv.y - cv.y, dz = xv.z - cv.z, dw = xv.w - cv.w;
    float s = dx * dx + dy * dy + dz * dz + dw * dw;
    #pragma unroll
    for (int off = 16; off > 0; off >>= 1)
        s += __shfl_down_sync(0xFFFFFFFFu, s, off);
    if ((t & 31) == 0) s_warp[t >> 5] = s;
    __syncthreads();
    if (t == 0)
        result[b] = s_warp[0] + s_warp[1] + s_warp[2] + s_warp[3];
}

// ---------------------------------------------------------------- K3: fused streaming output pass
// 8 class rows per block, 256 threads, 4 float4s per thread (MLP=4).
// new_centers[c] = centers[c]*scale(cnt) + (a/(cnt+1)) * sum_{label[s]==c} x[s]
// Touched blocks (<=253 of 6250) additionally scan the 256 labels from shared
// and gather matching x rows directly from gmem.
__global__ __launch_bounds__(256) void k_centers(const float4* __restrict__ centers,
                                                 const float* __restrict__ x,
                                                 float4* __restrict__ out) {
    __shared__ float s_scale[ROWS_PB], s_inv[ROWS_PB];
    __shared__ int   s_cnt[ROWS_PB];
    __shared__ int   s_labels[NB];
    __shared__ int   s_any;

    int t = threadIdx.x;
    int row0 = blockIdx.x * ROWS_PB;

    if (t < ROWS_PB) {
        int cnt = g_counts[row0 + t];
        float fc = (float)cnt;
        float inv = ALPHA_F / (fc + 1.0f);
        s_cnt[t] = cnt;
        s_inv[t] = inv;
        s_scale[t] = 1.0f - inv * fc;
    }
    __syncthreads();
    if (t == 0) {
        int any = 0;
        #pragma unroll
        for (int r = 0; r < ROWS_PB; r++) any |= s_cnt[r];
        s_any = any;
    }
    __syncthreads();
    if (s_any) {                        // uniform per block
        s_labels[t] = g_labels[t];      // NB == 256 == blockDim
        __syncthreads();
    }

    size_t base = (size_t)blockIdx.x * (ROWS_PB * ND4);   // 1024 float4 per block
    float4 v0 = __ldcs(centers + base + t);
    float4 v1 = __ldcs(centers + base + t + 256);
    float4 v2 = __ldcs(centers + base + t + 512);
    float4 v3 = __ldcs(centers + base + t + 768);

    int r0 = t >> 7;          // 0..1
    int r1 = r0 + 2;
    int r2 = r0 + 4;
    int r3 = r0 + 6;
    int col = (t & 127);      // float4 column within row

    float sc;
    sc = s_scale[r0]; v0.x *= sc; v0.y *= sc; v0.z *= sc; v0.w *= sc;
    sc = s_scale[r1]; v1.x *= sc; v1.y *= sc; v1.z *= sc; v1.w *= sc;
    sc = s_scale[r2]; v2.x *= sc; v2.y *= sc; v2.z *= sc; v2.w *= sc;
    sc = s_scale[r3]; v3.x *= sc; v3.y *= sc; v3.z *= sc; v3.w *= sc;

    if (s_any) {
        // gather x rows for touched classes among this block's 8 rows
        for (int s = 0; s < NB; s++) {
            int rel = s_labels[s] - row0;
            if ((unsigned)rel < (unsigned)ROWS_PB) {
                // does this thread own (row=rel, col)?  thread owns rows r0,r1,r2,r3
                if (rel == r0 || rel == r1 || rel == r2 || rel == r3) {
                    float4 xv = *(const float4*)(x + (size_t)s * ND + col * 4);
                    float inv = s_inv[rel];
                    if (rel == r0) { v0.x += inv * xv.x; v0.y += inv * xv.y; v0.z += inv * xv.z; v0.w += inv * xv.w; }
                    else if (rel == r1) { v1.x += inv * xv.x; v1.y += inv * xv.y; v1.z += inv * xv.z; v1.w += inv * xv.w; }
                    else if (rel == r2) { v2.x += inv * xv.x; v2.y += inv * xv.y; v2.z += inv * xv.z; v2.w += inv * xv.w; }
                    else                { v3.x += inv * xv.x; v3.y += inv * xv.y; v3.z += inv * xv.z; v3.w += inv * xv.w; }
                }
            }
        }
    }

    __stcs(out + base + t,       v0);
    __stcs(out + base + t + 256, v1);
    __stcs(out + base + t + 512, v2);
    __stcs(out + base + t + 768, v3);
}

// ---------------------------------------------------------------- launch
extern "C" void kernel_launch(void* const* d_in, const int* in_sizes, int n_in,
                              void* d_out, int out_size) {
    const float* x       = (const float*)d_in[0];   // [256, 512]
    const float* onehot  = (const float*)d_in[1];   // [256, 50000]
    const float* centers = (const float*)d_in[2];   // [50000, 512]

    float* result      = (float*)d_out;             // [256]
    float* new_centers = (float*)d_out + NB;        // [50000, 512]

    k_zero<<<(NC + 255) / 256, 256>>>();
    k_find<<<(NB * NC / 4) / 1024, 256>>>((const float4*)onehot);
    k_sample<<<NB, ND4>>>(x, centers, result);
    k_centers<<<NC / ROWS_PB, 256>>>((const float4*)centers, x, (float4*)new_centers);
}